// round 12
// baseline (speedup 1.0000x reference)
#include <cuda_runtime.h>
#include <cuda_bf16.h>

// LIF scan, T=4, V_RESET=0, TAU=2, forward spike = heaviside(v_charged - 1).
// FINAL — converged at the measured DRAM/LTS streaming ceiling. This exact
// binary holds the wall record (92.64us; kernel 85.79-86.47 over 6 runs).
//   - 1 float4/thread, 4 front-batched LDG.128 (MLP=4), .cs streaming hints
//   - block=512, one-shot CTAs, 9456 blocks (exact division, no tail)
// Sweep evidence (kernel us): block 128->87.58, 256->86.66,
// 512->85.92/86.46/85.79/86.30/86.37, 1024->86.72; 2x ILP -> 94.69 (regs 42,
// occ 51%); persistent grid -> 93.86 (backedge breaks load front-batching);
// cache hints neutral. 620 MB irreducible traffic @ 6.55-6.59 TB/s =
// 82-83% of HBM spec = path-independent LTS cap (TMA shares the ceiling).

#define T_STEPS 4

__device__ __forceinline__ void lif_step(float& v, float x, float& s) {
    // Match reference arithmetic exactly: v_charged = v + (x - v)/2
    float vc = fmaf(x - v, 0.5f, v);
    bool sp = (vc >= 1.0f);           // v_charged - V_THRESHOLD >= 0
    s = sp ? 1.0f : 0.0f;
    v = sp ? 0.0f : vc;               // hard reset to V_RESET=0
}

__global__ void __launch_bounds__(512)
lif_kernel(const float4* __restrict__ x, float4* __restrict__ out, int n4) {
    int i = blockIdx.x * blockDim.x + threadIdx.x;
    if (i >= n4) return;

    // Front-batched streaming loads: independent of the v-chain (MLP=4).
    float4 x0 = __ldcs(x + i);
    float4 x1 = __ldcs(x + i + (size_t)n4);
    float4 x2 = __ldcs(x + i + (size_t)2 * n4);
    float4 x3 = __ldcs(x + i + (size_t)3 * n4);

    float4 s0, s1, s2, s3;

    // 4 independent lanes, each a 4-step sequential scan.
    {
        float v = 0.0f;
        lif_step(v, x0.x, s0.x); lif_step(v, x1.x, s1.x);
        lif_step(v, x2.x, s2.x); lif_step(v, x3.x, s3.x);
    }
    {
        float v = 0.0f;
        lif_step(v, x0.y, s0.y); lif_step(v, x1.y, s1.y);
        lif_step(v, x2.y, s2.y); lif_step(v, x3.y, s3.y);
    }
    {
        float v = 0.0f;
        lif_step(v, x0.z, s0.z); lif_step(v, x1.z, s1.z);
        lif_step(v, x2.z, s2.z); lif_step(v, x3.z, s3.z);
    }
    {
        float v = 0.0f;
        lif_step(v, x0.w, s0.w); lif_step(v, x1.w, s1.w);
        lif_step(v, x2.w, s2.w); lif_step(v, x3.w, s3.w);
    }

    __stcs(out + i,                  s0);
    __stcs(out + i + (size_t)n4,     s1);
    __stcs(out + i + (size_t)2 * n4, s2);
    __stcs(out + i + (size_t)3 * n4, s3);
}

extern "C" void kernel_launch(void* const* d_in, const int* in_sizes, int n_in,
                              void* d_out, int out_size) {
    const float* x = (const float*)d_in[0];
    float* out = (float*)d_out;

    int total = in_sizes[0];             // T * N = 77,463,552
    int n = total / T_STEPS;             // 19,365,888 elements per timestep
    int n4 = n / 4;                      // 4,841,472 float4 lanes (divisible by 512)

    int threads = 512;
    int blocks = (n4 + threads - 1) / threads;   // 9,456 CTAs, no partial tail
    lif_kernel<<<blocks, threads>>>((const float4*)x, (float4*)out, n4);
}

// round 13
// speedup vs baseline: 1.0003x; 1.0003x over previous
#include <cuda_runtime.h>
#include <cuda_bf16.h>

// LIF scan, T=4, V_RESET=0, TAU=2, forward spike = heaviside(v_charged - 1).
// FINAL — converged at the measured DRAM/LTS streaming ceiling.
// Wall record 92.64us; kernel 85.79-86.47us over 7 replicates.
//   - 1 float4/thread, 4 front-batched LDG.128 (MLP=4), .cs streaming hints
//   - block=512, one-shot CTAs, 9456 blocks (exact division, no tail)
// Sweep evidence (kernel us): block 128->87.58, 256->86.66,
// 512->85.92/86.46/85.79/86.30/86.37/85.95, 1024->86.72; 2x ILP -> 94.69
// (regs 42, occ 51%); persistent grid -> 93.86 (backedge breaks load
// front-batching); cache hints neutral. 620 MB irreducible traffic @
// 6.55-6.59 TB/s = 82-83% of HBM spec = path-independent LTS cap.

#define T_STEPS 4

__device__ __forceinline__ void lif_step(float& v, float x, float& s) {
    // Match reference arithmetic exactly: v_charged = v + (x - v)/2
    float vc = fmaf(x - v, 0.5f, v);
    bool sp = (vc >= 1.0f);           // v_charged - V_THRESHOLD >= 0
    s = sp ? 1.0f : 0.0f;
    v = sp ? 0.0f : vc;               // hard reset to V_RESET=0
}

__global__ void __launch_bounds__(512)
lif_kernel(const float4* __restrict__ x, float4* __restrict__ out, int n4) {
    int i = blockIdx.x * blockDim.x + threadIdx.x;
    if (i >= n4) return;

    // Front-batched streaming loads: independent of the v-chain (MLP=4).
    float4 x0 = __ldcs(x + i);
    float4 x1 = __ldcs(x + i + (size_t)n4);
    float4 x2 = __ldcs(x + i + (size_t)2 * n4);
    float4 x3 = __ldcs(x + i + (size_t)3 * n4);

    float4 s0, s1, s2, s3;

    // 4 independent lanes, each a 4-step sequential scan.
    {
        float v = 0.0f;
        lif_step(v, x0.x, s0.x); lif_step(v, x1.x, s1.x);
        lif_step(v, x2.x, s2.x); lif_step(v, x3.x, s3.x);
    }
    {
        float v = 0.0f;
        lif_step(v, x0.y, s0.y); lif_step(v, x1.y, s1.y);
        lif_step(v, x2.y, s2.y); lif_step(v, x3.y, s3.y);
    }
    {
        float v = 0.0f;
        lif_step(v, x0.z, s0.z); lif_step(v, x1.z, s1.z);
        lif_step(v, x2.z, s2.z); lif_step(v, x3.z, s3.z);
    }
    {
        float v = 0.0f;
        lif_step(v, x0.w, s0.w); lif_step(v, x1.w, s1.w);
        lif_step(v, x2.w, s2.w); lif_step(v, x3.w, s3.w);
    }

    __stcs(out + i,                  s0);
    __stcs(out + i + (size_t)n4,     s1);
    __stcs(out + i + (size_t)2 * n4, s2);
    __stcs(out + i + (size_t)3 * n4, s3);
}

extern "C" void kernel_launch(void* const* d_in, const int* in_sizes, int n_in,
                              void* d_out, int out_size) {
    const float* x = (const float*)d_in[0];
    float* out = (float*)d_out;

    int total = in_sizes[0];             // T * N = 77,463,552
    int n = total / T_STEPS;             // 19,365,888 elements per timestep
    int n4 = n / 4;                      // 4,841,472 float4 lanes (divisible by 512)

    int threads = 512;
    int blocks = (n4 + threads - 1) / threads;   // 9,456 CTAs, no partial tail
    lif_kernel<<<blocks, threads>>>((const float4*)x, (float4*)out, n4);
}